// round 9
// baseline (speedup 1.0000x reference)
#include <cuda_runtime.h>
#include <cuda_fp16.h>
#include <math.h>
#include <stdint.h>

#define B_ 4
#define N_ 2048
#define C_ 1024
#define M_TOT (B_ * N_)   // 8192

// ---------------- scratch (__device__ globals; no allocation) ----------------
__device__ __align__(128) __half g_hh[(size_t)M_TOT * C_];
__device__ __align__(128) __half g_Wqh[C_ * C_], g_Wkh[C_ * C_], g_Wvh[C_ * C_];
__device__ __align__(128) __half g_Q[(size_t)M_TOT * C_];
__device__ __align__(128) __half g_K[(size_t)M_TOT * C_];
__device__ __align__(128) __half g_VT[(size_t)C_ * M_TOT];   // [C_, M_TOT]
__device__ __align__(128) __half g_P[(size_t)B_ * N_ * N_];

// ---------------- portable PTX helpers (base-target safe) ----------------
__device__ __forceinline__ uint32_t smem_u32(const void* p) {
    uint32_t a;
    asm("{ .reg .u64 t; cvta.to.shared.u64 t, %1; cvt.u32.u64 %0, t; }" : "=r"(a) : "l"(p));
    return a;
}
__device__ __forceinline__ void cp_async16(uint32_t dst, const void* src) {
    asm volatile("cp.async.cg.shared.global [%0], [%1], 16;" :: "r"(dst), "l"(src) : "memory");
}
#define CP_COMMIT()  asm volatile("cp.async.commit_group;" ::: "memory")
#define CP_WAIT(n)   asm volatile("cp.async.wait_group %0;" :: "n"(n) : "memory")

__device__ __forceinline__ void ldsm_x4(uint32_t& r0, uint32_t& r1, uint32_t& r2, uint32_t& r3,
                                        uint32_t addr) {
    asm volatile("ldmatrix.sync.aligned.m8n8.x4.shared.b16 {%0,%1,%2,%3}, [%4];"
                 : "=r"(r0), "=r"(r1), "=r"(r2), "=r"(r3) : "r"(addr));
}
__device__ __forceinline__ void mma16816(float* d, const uint32_t* a, const uint32_t* b) {
    asm volatile(
        "mma.sync.aligned.m16n8k16.row.col.f32.f16.f16.f32 "
        "{%0,%1,%2,%3}, {%4,%5,%6,%7}, {%8,%9}, {%0,%1,%2,%3};"
        : "+f"(d[0]), "+f"(d[1]), "+f"(d[2]), "+f"(d[3])
        : "r"(a[0]), "r"(a[1]), "r"(a[2]), "r"(a[3]), "r"(b[0]), "r"(b[1]));
}
__device__ __forceinline__ uint32_t swz(uint32_t off) { return off ^ ((off >> 3) & 0x70); }

// ---------------- fp16 single-pass HMMA GEMM: D = alpha*(A @ B^T) (+bias) ----------------
// Block tile 128x256, BK=64 (128B rows); 512 threads = 16 warps as 4(m) x 4(n),
// warp tile 32x64 -> 4 warps per SMSP for latency hiding.
#define BM_ 128
#define BN_ 256
#define STAGES 3
#define TILE_A_BYTES 16384         // 128 rows * 128 B
#define STAGE_BYTES  49152
#define SMEM_GEMM (STAGES * STAGE_BYTES)   // 144 KB
#define NTHREADS 512

__global__ __launch_bounds__(NTHREADS, 1) void gemm_fp16(
    const __half* __restrict__ A, const __half* __restrict__ Bm,
    int lda, int ldb, long long batA, long long batB, int K,
    float* __restrict__ Cf, long long batCf, int ldc,
    __half* __restrict__ Ch, long long batCh,
    float alpha, const float* __restrict__ bias, int bias_mode)
{
    extern __shared__ char smem[];
    const uint32_t sbase = smem_u32(smem);
    const int tid  = threadIdx.x;
    const int wid  = tid >> 5;
    const int lane = tid & 31;
    const long long bz = blockIdx.z;
    const int m0 = blockIdx.y * BM_;
    const int n0 = blockIdx.x * BN_;

    const __half* Ap = A + bz * batA;
    const __half* Bp = Bm + bz * batB;

    // 16 warps: 4 (m) x 4 (n); warp tile 32x64
    const int wm = (wid >> 2) * 32;
    const int wn = (wid & 3) * 64;

    const int NK = K >> 6;     // K/64 chunks

    const int lrow = tid >> 3;   // 0..63
    const int lch  = tid & 7;

    auto load_stage = [&](int kc, int s) {
        const __half* Asrc = Ap + (size_t)m0 * lda + kc * 64;
        const __half* Bsrc = Bp + (size_t)n0 * ldb + kc * 64;
        const uint32_t sa = sbase + s * STAGE_BYTES;
        const uint32_t sb = sa + TILE_A_BYTES;
        #pragma unroll
        for (int r = 0; r < 2; r++) {            // 128 A rows, 64 per iter
            int row = r * 64 + lrow;
            uint32_t sw = swz(row * 128 + lch * 16);
            cp_async16(sa + sw, Asrc + (size_t)row * lda + lch * 8);
        }
        #pragma unroll
        for (int r = 0; r < 4; r++) {            // 256 B rows
            int row = r * 64 + lrow;
            uint32_t sw = swz(row * 128 + lch * 16);
            cp_async16(sb + sw, Bsrc + (size_t)row * ldb + lch * 8);
        }
        CP_COMMIT();
    };

    float acc[2][8][4];
    #pragma unroll
    for (int i = 0; i < 2; i++)
        #pragma unroll
        for (int j = 0; j < 8; j++)
            #pragma unroll
            for (int e = 0; e < 4; e++) acc[i][j][e] = 0.f;

    const int a_row_l = ((lane >> 3) & 1) * 8 + (lane & 7);
    const int a_col_l = ((lane >> 4) & 1) * 16;
    const int b_row_l = ((lane >> 4) & 1) * 8 + (lane & 7);
    const int b_col_l = ((lane >> 3) & 1) * 16;

    #pragma unroll
    for (int i = 0; i < STAGES; i++)
        if (i < NK) load_stage(i, i);

    int s = 0;
    for (int kc = 0; kc < NK; kc++) {
        int rem = NK - 1 - kc;
        if (rem >= 2)      { CP_WAIT(2); }
        else if (rem == 1) { CP_WAIT(1); }
        else               { CP_WAIT(0); }
        __syncthreads();

        const uint32_t cur_sa = sbase + s * STAGE_BYTES;
        const uint32_t cur_sb = cur_sa + TILE_A_BYTES;

        #pragma unroll
        for (int k16 = 0; k16 < 4; k16++) {
            uint32_t a[2][4], b[8][2];
            #pragma unroll
            for (int mt = 0; mt < 2; mt++) {
                uint32_t off = (uint32_t)(wm + mt * 16 + a_row_l) * 128 + k16 * 32 + a_col_l;
                ldsm_x4(a[mt][0], a[mt][1], a[mt][2], a[mt][3], cur_sa + swz(off));
            }
            #pragma unroll
            for (int nt2 = 0; nt2 < 4; nt2++) {
                uint32_t off = (uint32_t)(wn + nt2 * 16 + b_row_l) * 128 + k16 * 32 + b_col_l;
                uint32_t r0, r1, r2, r3;
                ldsm_x4(r0, r1, r2, r3, cur_sb + swz(off));
                b[nt2 * 2 + 0][0] = r0; b[nt2 * 2 + 0][1] = r1;
                b[nt2 * 2 + 1][0] = r2; b[nt2 * 2 + 1][1] = r3;
            }
            #pragma unroll
            for (int mt = 0; mt < 2; mt++)
                #pragma unroll
                for (int nt = 0; nt < 8; nt++)
                    mma16816(acc[mt][nt], a[mt], b[nt]);
        }

        __syncthreads();
        if (kc + STAGES < NK) load_stage(kc + STAGES, s);
        s++;
        if (s == STAGES) s = 0;
    }

    // ---------------- epilogue ----------------
    const int erow = lane >> 2;
    const int ecol = (lane & 3) * 2;

    #pragma unroll
    for (int mt = 0; mt < 2; mt++) {
        #pragma unroll
        for (int h = 0; h < 2; h++) {
            const int gm = m0 + wm + mt * 16 + h * 8 + erow;
            float brow = (bias_mode == 2) ? bias[gm] : 0.f;
            #pragma unroll
            for (int nt = 0; nt < 8; nt++) {
                const int gn = n0 + wn + nt * 8 + ecol;
                float x0 = acc[mt][nt][h * 2 + 0] * alpha;
                float x1 = acc[mt][nt][h * 2 + 1] * alpha;
                if (bias_mode == 1) { x0 += bias[gn]; x1 += bias[gn + 1]; }
                else if (bias_mode == 2) { x0 += brow; x1 += brow; }
                if (Cf) {
                    float2 v; v.x = x0; v.y = x1;
                    *(float2*)(Cf + bz * batCf + (size_t)gm * ldc + gn) = v;
                } else {
                    __half2 hv = __floats2half2_rn(x0, x1);
                    *(__half2*)(Ch + bz * batCh + (size_t)gm * ldc + gn) = hv;
                }
            }
        }
    }
}

// ---------------- elementwise kernels ----------------
__global__ __launch_bounds__(256) void cast_fp16(
    const float* __restrict__ x, __half* __restrict__ y, size_t n4)
{
    size_t i = ((size_t)blockIdx.x * blockDim.x + threadIdx.x);
    if (i >= n4) return;
    float4 v = *(const float4*)(x + i * 4);
    __half2 h0 = __floats2half2_rn(v.x, v.y);
    __half2 h1 = __floats2half2_rn(v.z, v.w);
    uint2 u;
    u.x = *(uint32_t*)&h0;
    u.y = *(uint32_t*)&h1;
    *(uint2*)(y + i * 4) = u;
}

// softmax over rows of 2048 fp32, in-place, plus fp16 copy.
__global__ __launch_bounds__(256) void softmax_h(
    float* __restrict__ P, __half* __restrict__ Ph)
{
    const size_t row = blockIdx.x;
    float* p = P + row * (size_t)N_;
    __half* ph = Ph + row * (size_t)N_;
    const int tid = threadIdx.x;
    const int lane = tid & 31;
    const int warp = tid >> 5;

    float vals[8];
    float m = -INFINITY;
    #pragma unroll
    for (int i = 0; i < 8; i++) {
        vals[i] = p[tid + i * 256];
        m = fmaxf(m, vals[i]);
    }
    __shared__ float redmax[8], redsum[8];
    #pragma unroll
    for (int off = 16; off > 0; off >>= 1)
        m = fmaxf(m, __shfl_xor_sync(0xffffffffu, m, off));
    if (lane == 0) redmax[warp] = m;
    __syncthreads();
    float rowmax = redmax[0];
    #pragma unroll
    for (int w = 1; w < 8; w++) rowmax = fmaxf(rowmax, redmax[w]);

    float sum = 0.f;
    #pragma unroll
    for (int i = 0; i < 8; i++) {
        vals[i] = expf(vals[i] - rowmax);
        sum += vals[i];
    }
    #pragma unroll
    for (int off = 16; off > 0; off >>= 1)
        sum += __shfl_xor_sync(0xffffffffu, sum, off);
    if (lane == 0) redsum[warp] = sum;
    __syncthreads();
    float total = 0.f;
    #pragma unroll
    for (int w = 0; w < 8; w++) total += redsum[w];
    float inv = 1.f / total;

    #pragma unroll
    for (int i = 0; i < 8; i++) {
        float v = vals[i] * inv;
        p[tid + i * 256] = v;
        ph[tid + i * 256] = __float2half(v);
    }
}

// ---------------- launch ----------------
extern "C" void kernel_launch(void* const* d_in, const int* in_sizes, int n_in,
                              void* d_out, int out_size)
{
    const float* h  = (const float*)d_in[0];
    const float* Wq = (const float*)d_in[1];
    const float* bq = (const float*)d_in[2];
    const float* Wk = (const float*)d_in[3];
    const float* bk = (const float*)d_in[4];
    const float* Wv = (const float*)d_in[5];
    const float* bv = (const float*)d_in[6];

    float* out  = (float*)d_out;                 // [B,N,C]
    float* attn = out + (size_t)B_ * N_ * C_;    // [B,N,N]

    __half *hh, *Wqh, *Wkh, *Wvh, *Q, *K, *VT, *P;
    cudaGetSymbolAddress((void**)&hh, g_hh);
    cudaGetSymbolAddress((void**)&Wqh, g_Wqh);
    cudaGetSymbolAddress((void**)&Wkh, g_Wkh);
    cudaGetSymbolAddress((void**)&Wvh, g_Wvh);
    cudaGetSymbolAddress((void**)&Q, g_Q);
    cudaGetSymbolAddress((void**)&K, g_K);
    cudaGetSymbolAddress((void**)&VT, g_VT);
    cudaGetSymbolAddress((void**)&P, g_P);

    cudaFuncSetAttribute(gemm_fp16, cudaFuncAttributeMaxDynamicSharedMemorySize, SMEM_GEMM);

    // 1) casts to fp16
    {
        size_t nh4 = (size_t)M_TOT * C_ / 4;
        cast_fp16<<<(unsigned)(nh4 / 256), 256>>>(h, hh, nh4);
        size_t nw4 = (size_t)C_ * C_ / 4;
        cast_fp16<<<(unsigned)(nw4 / 256), 256>>>(Wq, Wqh, nw4);
        cast_fp16<<<(unsigned)(nw4 / 256), 256>>>(Wk, Wkh, nw4);
        cast_fp16<<<(unsigned)(nw4 / 256), 256>>>(Wv, Wvh, nw4);
    }

    dim3 blk(NTHREADS);

    // 2) Q = h @ Wq^T + bq ; K = h @ Wk^T + bk  -> fp16
    {
        dim3 g(C_ / BN_, M_TOT / BM_, 1);
        gemm_fp16<<<g, blk, SMEM_GEMM>>>(hh, Wqh, C_, C_, 0, 0, C_,
                                         nullptr, 0, C_, Q, 0, 1.0f, bq, 1);
        gemm_fp16<<<g, blk, SMEM_GEMM>>>(hh, Wkh, C_, C_, 0, 0, C_,
                                         nullptr, 0, C_, K, 0, 1.0f, bk, 1);
    }
    // 3) V^T = Wv @ h^T + bv (row bias) -> fp16 [C_, M_TOT]
    {
        dim3 g(M_TOT / BN_, C_ / BM_, 1);
        gemm_fp16<<<g, blk, SMEM_GEMM>>>(Wvh, hh, C_, C_, 0, 0, C_,
                                         nullptr, 0, M_TOT, VT, 0, 1.0f, bv, 2);
    }
    // 4) scores = (Q @ K^T) / 32 -> fp32 attn (per batch)
    {
        dim3 g(N_ / BN_, N_ / BM_, B_);
        gemm_fp16<<<g, blk, SMEM_GEMM>>>(
            Q, K, C_, C_,
            (long long)N_ * C_, (long long)N_ * C_, C_,
            attn, (long long)N_ * N_, N_,
            nullptr, 0, 1.0f / 32.0f, nullptr, 0);
    }
    // 5) softmax (in place) + fp16 copy
    softmax_h<<<B_ * N_, 256>>>(attn, P);

    // 6) out = P @ (V^T)^T (per batch: M=2048, N=1024, K=2048)
    {
        dim3 g(C_ / BN_, N_ / BM_, B_);
        gemm_fp16<<<g, blk, SMEM_GEMM>>>(
            P, VT, N_, M_TOT,
            (long long)N_ * N_, (long long)N_, N_,
            out, (long long)N_ * C_, C_,
            nullptr, 0, 1.0f, nullptr, 0);
    }
}

// round 10
// speedup vs baseline: 1.1025x; 1.1025x over previous
#include <cuda_runtime.h>
#include <cuda_fp16.h>
#include <math.h>
#include <stdint.h>

#define B_ 4
#define N_ 2048
#define C_ 1024
#define M_TOT (B_ * N_)   // 8192

// ---------------- scratch (__device__ globals; no allocation) ----------------
__device__ __align__(128) __half g_hh[(size_t)M_TOT * C_];
__device__ __align__(128) __half g_Wvh[C_ * C_];
__device__ __align__(128) __half g_WqT[C_ * C_];     // Wq^T fp16 [in,out]
__device__ __align__(128) __half g_WkT[C_ * C_];     // Wk^T fp16 [in,out]
__device__ __align__(128) __half g_MT[C_ * C_];      // (Wq^T Wk)^T fp16
__device__ __align__(128) __half g_QM[(size_t)M_TOT * C_];   // h @ M
__device__ __align__(128) __half g_VT[(size_t)C_ * M_TOT];   // [C_, M_TOT]
__device__ __align__(128) __half g_P[(size_t)B_ * N_ * N_];
__device__ float g_w1[C_], g_w2[C_];
__device__ float g_u32[M_TOT], g_v32[M_TOT];
__device__ float g_cc;

// ---------------- portable PTX helpers (base-target safe) ----------------
__device__ __forceinline__ uint32_t smem_u32(const void* p) {
    uint32_t a;
    asm("{ .reg .u64 t; cvta.to.shared.u64 t, %1; cvt.u32.u64 %0, t; }" : "=r"(a) : "l"(p));
    return a;
}
__device__ __forceinline__ void cp_async16(uint32_t dst, const void* src) {
    asm volatile("cp.async.cg.shared.global [%0], [%1], 16;" :: "r"(dst), "l"(src) : "memory");
}
#define CP_COMMIT()  asm volatile("cp.async.commit_group;" ::: "memory")
#define CP_WAIT(n)   asm volatile("cp.async.wait_group %0;" :: "n"(n) : "memory")

__device__ __forceinline__ void ldsm_x4(uint32_t& r0, uint32_t& r1, uint32_t& r2, uint32_t& r3,
                                        uint32_t addr) {
    asm volatile("ldmatrix.sync.aligned.m8n8.x4.shared.b16 {%0,%1,%2,%3}, [%4];"
                 : "=r"(r0), "=r"(r1), "=r"(r2), "=r"(r3) : "r"(addr));
}
__device__ __forceinline__ void mma16816(float* d, const uint32_t* a, const uint32_t* b) {
    asm volatile(
        "mma.sync.aligned.m16n8k16.row.col.f32.f16.f16.f32 "
        "{%0,%1,%2,%3}, {%4,%5,%6,%7}, {%8,%9}, {%0,%1,%2,%3};"
        : "+f"(d[0]), "+f"(d[1]), "+f"(d[2]), "+f"(d[3])
        : "r"(a[0]), "r"(a[1]), "r"(a[2]), "r"(a[3]), "r"(b[0]), "r"(b[1]));
}
__device__ __forceinline__ uint32_t swz(uint32_t off) { return off ^ ((off >> 3) & 0x70); }

// ---------------- segmented fp16 GEMM: D = alpha*(A @ B^T) (+bias) ----------------
// Block tile 128x256, BK=64 (128B rows); 256 threads = 8 warps 2(m)x4(n), warp 64x64.
// Two segments per launch (1-D grid): blockIdx.x < n0 -> seg0, else seg1.
#define BM_ 128
#define BN_ 256
#define STAGES 3
#define TILE_A_BYTES 16384
#define STAGE_BYTES  49152
#define SMEM_GEMM (STAGES * STAGE_BYTES)   // 144 KB

struct GemmSeg {
    const __half* A; const __half* B;
    long long batA, batB, batC;
    int lda, ldb, ldc, K;
    float* Cf; __half* Ch;
    float alpha;
    const float* bias; int bias_mode;   // 0 none, 1 per-col, 2 per-row
    int gx, gxy;                        // n-tiles, n-tiles*m-tiles
};

__global__ __launch_bounds__(256, 1) void gemm_seg(GemmSeg s0, GemmSeg s1, int n0cnt)
{
    extern __shared__ char smem[];
    const uint32_t sbase = smem_u32(smem);
    const int tid  = threadIdx.x;
    const int wid  = tid >> 5;
    const int lane = tid & 31;

    const bool f = (int)blockIdx.x < n0cnt;
    const __half* Ag = f ? s0.A : s1.A;
    const __half* Bg = f ? s0.B : s1.B;
    const long long batA = f ? s0.batA : s1.batA;
    const long long batB = f ? s0.batB : s1.batB;
    const long long batC = f ? s0.batC : s1.batC;
    const int lda = f ? s0.lda : s1.lda;
    const int ldb = f ? s0.ldb : s1.ldb;
    const int ldc = f ? s0.ldc : s1.ldc;
    const int K   = f ? s0.K   : s1.K;
    float* Cf = f ? s0.Cf : s1.Cf;
    __half* Ch = f ? s0.Ch : s1.Ch;
    const float alpha = f ? s0.alpha : s1.alpha;
    const float* bias = f ? s0.bias : s1.bias;
    const int bias_mode = f ? s0.bias_mode : s1.bias_mode;
    const int gx  = f ? s0.gx  : s1.gx;
    const int gxy = f ? s0.gxy : s1.gxy;

    int lid = blockIdx.x - (f ? 0 : n0cnt);
    const long long bz = lid / gxy;
    int r = lid - (int)bz * gxy;
    const int m0 = (r / gx) * BM_;
    const int n0 = (r % gx) * BN_;

    const __half* Ap = Ag + bz * batA;
    const __half* Bp = Bg + bz * batB;

    const int wm = (wid >> 2) * 64;
    const int wn = (wid & 3) * 64;

    const int NK = K >> 6;

    const int lrow = tid >> 3;
    const int lch  = tid & 7;

    auto load_stage = [&](int kc, int s) {
        const __half* Asrc = Ap + (size_t)m0 * lda + kc * 64;
        const __half* Bsrc = Bp + (size_t)n0 * ldb + kc * 64;
        const uint32_t sa = sbase + s * STAGE_BYTES;
        const uint32_t sb = sa + TILE_A_BYTES;
        #pragma unroll
        for (int rr = 0; rr < 4; rr++) {
            int row = rr * 32 + lrow;
            uint32_t sw = swz(row * 128 + lch * 16);
            cp_async16(sa + sw, Asrc + (size_t)row * lda + lch * 8);
        }
        #pragma unroll
        for (int rr = 0; rr < 8; rr++) {
            int row = rr * 32 + lrow;
            uint32_t sw = swz(row * 128 + lch * 16);
            cp_async16(sb + sw, Bsrc + (size_t)row * ldb + lch * 8);
        }
        CP_COMMIT();
    };

    float acc[4][8][4];
    #pragma unroll
    for (int i = 0; i < 4; i++)
        #pragma unroll
        for (int j = 0; j < 8; j++)
            #pragma unroll
            for (int e = 0; e < 4; e++) acc[i][j][e] = 0.f;

    const int a_row_l = ((lane >> 3) & 1) * 8 + (lane & 7);
    const int a_col_l = ((lane >> 4) & 1) * 16;
    const int b_row_l = ((lane >> 4) & 1) * 8 + (lane & 7);
    const int b_col_l = ((lane >> 3) & 1) * 16;

    #pragma unroll
    for (int i = 0; i < STAGES; i++)
        if (i < NK) load_stage(i, i);

    int s = 0;
    for (int kc = 0; kc < NK; kc++) {
        int rem = NK - 1 - kc;
        if (rem >= 2)      { CP_WAIT(2); }
        else if (rem == 1) { CP_WAIT(1); }
        else               { CP_WAIT(0); }
        __syncthreads();

        const uint32_t cur_sa = sbase + s * STAGE_BYTES;
        const uint32_t cur_sb = cur_sa + TILE_A_BYTES;

        #pragma unroll
        for (int k16 = 0; k16 < 4; k16++) {
            uint32_t a[4][4], b[8][2];
            #pragma unroll
            for (int mt = 0; mt < 4; mt++) {
                uint32_t off = (uint32_t)(wm + mt * 16 + a_row_l) * 128 + k16 * 32 + a_col_l;
                ldsm_x4(a[mt][0], a[mt][1], a[mt][2], a[mt][3], cur_sa + swz(off));
            }
            #pragma unroll
            for (int nt2 = 0; nt2 < 4; nt2++) {
                uint32_t off = (uint32_t)(wn + nt2 * 16 + b_row_l) * 128 + k16 * 32 + b_col_l;
                uint32_t r0, r1, r2, r3;
                ldsm_x4(r0, r1, r2, r3, cur_sb + swz(off));
                b[nt2 * 2 + 0][0] = r0; b[nt2 * 2 + 0][1] = r1;
                b[nt2 * 2 + 1][0] = r2; b[nt2 * 2 + 1][1] = r3;
            }
            #pragma unroll
            for (int mt = 0; mt < 4; mt++)
                #pragma unroll
                for (int nt = 0; nt < 8; nt++)
                    mma16816(acc[mt][nt], a[mt], b[nt]);
        }

        __syncthreads();
        if (kc + STAGES < NK) load_stage(kc + STAGES, s);
        s++;
        if (s == STAGES) s = 0;
    }

    // epilogue
    const int erow = lane >> 2;
    const int ecol = (lane & 3) * 2;

    #pragma unroll
    for (int mt = 0; mt < 4; mt++) {
        #pragma unroll
        for (int h = 0; h < 2; h++) {
            const int gm = m0 + wm + mt * 16 + h * 8 + erow;
            float brow = (bias_mode == 2) ? bias[gm] : 0.f;
            #pragma unroll
            for (int nt = 0; nt < 8; nt++) {
                const int gn = n0 + wn + nt * 8 + ecol;
                float x0 = acc[mt][nt][h * 2 + 0] * alpha;
                float x1 = acc[mt][nt][h * 2 + 1] * alpha;
                if (bias_mode == 1) { x0 += bias[gn]; x1 += bias[gn + 1]; }
                else if (bias_mode == 2) { x0 += brow; x1 += brow; }
                if (Cf) {
                    float2 v; v.x = x0; v.y = x1;
                    *(float2*)(Cf + bz * batC + (size_t)gm * ldc + gn) = v;
                } else {
                    __half2 hv = __floats2half2_rn(x0, x1);
                    *(__half2*)(Ch + bz * batC + (size_t)gm * ldc + gn) = hv;
                }
            }
        }
    }
}

// ---------------- elementwise / small kernels ----------------
__global__ __launch_bounds__(256) void cast_fp16(
    const float* __restrict__ x, __half* __restrict__ y, size_t n4)
{
    size_t i = ((size_t)blockIdx.x * blockDim.x + threadIdx.x);
    if (i >= n4) return;
    float4 v = *(const float4*)(x + i * 4);
    __half2 h0 = __floats2half2_rn(v.x, v.y);
    __half2 h1 = __floats2half2_rn(v.z, v.w);
    uint2 u;
    u.x = *(uint32_t*)&h0;
    u.y = *(uint32_t*)&h1;
    *(uint2*)(y + i * 4) = u;
}

// transpose + cast: in fp32 [R,C] -> out fp16 [C,R]
__global__ __launch_bounds__(256) void tcast(
    const float* __restrict__ in, __half* __restrict__ out, int R, int C)
{
    __shared__ __half tile[32][33];
    const int bx = blockIdx.x * 32;   // column offset in input
    const int by = blockIdx.y * 32;   // row offset in input
    const int tx = threadIdx.x & 31;
    const int ty = threadIdx.x >> 5;  // 0..7
    #pragma unroll
    for (int i = 0; i < 32; i += 8)
        tile[ty + i][tx] = __float2half(in[(size_t)(by + ty + i) * C + bx + tx]);
    __syncthreads();
    #pragma unroll
    for (int i = 0; i < 32; i += 8)
        out[(size_t)(bx + ty + i) * R + by + tx] = tile[tx][ty + i];
}

// w1_c = sum_d Wq[d][c]*bk[d];  w2_c = sum_d Wk[d][c]*bq[d];  cc = bq.bk
__global__ __launch_bounds__(256) void wvec(
    const float* __restrict__ Wq, const float* __restrict__ Wk,
    const float* __restrict__ bq, const float* __restrict__ bk)
{
    const int bid = blockIdx.x;
    if (bid < 8) {
        const float* W = (bid < 4) ? Wq : Wk;
        const float* bb = (bid < 4) ? bk : bq;
        float* dst = (bid < 4) ? g_w1 : g_w2;
        int c = (bid & 3) * 256 + threadIdx.x;
        float s = 0.f;
        for (int d = 0; d < C_; d++) s += W[(size_t)d * C_ + c] * bb[d];
        dst[c] = s;
    } else {
        // cc
        const int tid = threadIdx.x;
        float s = 0.f;
        for (int d = tid; d < C_; d += 256) s += bq[d] * bk[d];
        __shared__ float red[8];
        #pragma unroll
        for (int off = 16; off > 0; off >>= 1)
            s += __shfl_xor_sync(0xffffffffu, s, off);
        if ((tid & 31) == 0) red[tid >> 5] = s;
        __syncthreads();
        if (tid == 0) {
            float t = 0.f;
            for (int w = 0; w < 8; w++) t += red[w];
            g_cc = t;
        }
    }
}

// u32[i] = (h_i.w1 + cc)/32 ; v32[i] = (h_i.w2)/32   (one warp per row)
__global__ __launch_bounds__(256) void uvvec(const __half* __restrict__ hh)
{
    __shared__ float w1s[C_], w2s[C_];
    const int tid = threadIdx.x;
    for (int i = tid; i < C_; i += 256) { w1s[i] = g_w1[i]; w2s[i] = g_w2[i]; }
    __syncthreads();
    const int lane = tid & 31;
    const int warp = tid >> 5;
    const int row = blockIdx.x * 8 + warp;
    const __half* hr = hh + (size_t)row * C_;
    float s1 = 0.f, s2 = 0.f;
    for (int k = lane; k < C_; k += 32) {
        float a = __half2float(hr[k]);
        s1 += a * w1s[k];
        s2 += a * w2s[k];
    }
    #pragma unroll
    for (int off = 16; off > 0; off >>= 1) {
        s1 += __shfl_xor_sync(0xffffffffu, s1, off);
        s2 += __shfl_xor_sync(0xffffffffu, s2, off);
    }
    if (lane == 0) {
        g_u32[row] = (s1 + g_cc) * (1.0f / 32.0f);
        g_v32[row] = s2 * (1.0f / 32.0f);
    }
}

// softmax over rows of 2048 (adds rank-1 bias terms), in-place fp32 + fp16 copy.
__global__ __launch_bounds__(256) void softmax_h(
    float* __restrict__ P, __half* __restrict__ Ph)
{
    const size_t row = blockIdx.x;
    float* p = P + row * (size_t)N_;
    __half* ph = Ph + row * (size_t)N_;
    const float* vb = g_v32 + (row >> 11 << 11);   // batch base
    const float uadd = g_u32[row];
    const int tid = threadIdx.x;
    const int lane = tid & 31;
    const int warp = tid >> 5;

    float vals[8];
    float m = -INFINITY;
    #pragma unroll
    for (int i = 0; i < 8; i++) {
        int j = tid + i * 256;
        vals[i] = p[j] + uadd + vb[j];
        m = fmaxf(m, vals[i]);
    }
    __shared__ float redmax[8], redsum[8];
    #pragma unroll
    for (int off = 16; off > 0; off >>= 1)
        m = fmaxf(m, __shfl_xor_sync(0xffffffffu, m, off));
    if (lane == 0) redmax[warp] = m;
    __syncthreads();
    float rowmax = redmax[0];
    #pragma unroll
    for (int w = 1; w < 8; w++) rowmax = fmaxf(rowmax, redmax[w]);

    float sum = 0.f;
    #pragma unroll
    for (int i = 0; i < 8; i++) {
        vals[i] = __expf(vals[i] - rowmax);
        sum += vals[i];
    }
    #pragma unroll
    for (int off = 16; off > 0; off >>= 1)
        sum += __shfl_xor_sync(0xffffffffu, sum, off);
    if (lane == 0) redsum[warp] = sum;
    __syncthreads();
    float total = 0.f;
    #pragma unroll
    for (int w = 0; w < 8; w++) total += redsum[w];
    float inv = 1.f / total;

    #pragma unroll
    for (int i = 0; i < 8; i++) {
        float v = vals[i] * inv;
        p[tid + i * 256] = v;
        ph[tid + i * 256] = __float2half(v);
    }
}

// ---------------- launch ----------------
extern "C" void kernel_launch(void* const* d_in, const int* in_sizes, int n_in,
                              void* d_out, int out_size)
{
    const float* h  = (const float*)d_in[0];
    const float* Wq = (const float*)d_in[1];
    const float* bq = (const float*)d_in[2];
    const float* Wk = (const float*)d_in[3];
    const float* bk = (const float*)d_in[4];
    const float* Wv = (const float*)d_in[5];
    const float* bv = (const float*)d_in[6];

    float* out  = (float*)d_out;                 // [B,N,C]
    float* attn = out + (size_t)B_ * N_ * C_;    // [B,N,N]

    __half *hh, *Wvh, *WqT, *WkT, *MT, *QM, *VT, *P;
    cudaGetSymbolAddress((void**)&hh,  g_hh);
    cudaGetSymbolAddress((void**)&Wvh, g_Wvh);
    cudaGetSymbolAddress((void**)&WqT, g_WqT);
    cudaGetSymbolAddress((void**)&WkT, g_WkT);
    cudaGetSymbolAddress((void**)&MT,  g_MT);
    cudaGetSymbolAddress((void**)&QM,  g_QM);
    cudaGetSymbolAddress((void**)&VT,  g_VT);
    cudaGetSymbolAddress((void**)&P,   g_P);

    cudaFuncSetAttribute(gemm_seg, cudaFuncAttributeMaxDynamicSharedMemorySize, SMEM_GEMM);

    // 1) casts / transposes / bias vectors
    {
        size_t nh4 = (size_t)M_TOT * C_ / 4;
        cast_fp16<<<(unsigned)(nh4 / 256), 256>>>(h, hh, nh4);
        size_t nw4 = (size_t)C_ * C_ / 4;
        cast_fp16<<<(unsigned)(nw4 / 256), 256>>>(Wv, Wvh, nw4);
        dim3 tg(C_ / 32, C_ / 32);
        tcast<<<tg, 256>>>(Wq, WqT, C_, C_);
        tcast<<<tg, 256>>>(Wk, WkT, C_, C_);
        wvec<<<9, 256>>>(Wq, Wk, bq, bk);
        uvvec<<<M_TOT / 8, 256>>>(hh);
    }

    auto mkseg = [](const __half* A, const __half* B, long long bA, long long bB,
                    long long bC, int lda, int ldb, int ldc, int K,
                    float* Cf, __half* Ch, float alpha,
                    const float* bias, int bias_mode, int gx, int gy) {
        GemmSeg s;
        s.A = A; s.B = B; s.batA = bA; s.batB = bB; s.batC = bC;
        s.lda = lda; s.ldb = ldb; s.ldc = ldc; s.K = K;
        s.Cf = Cf; s.Ch = Ch; s.alpha = alpha; s.bias = bias; s.bias_mode = bias_mode;
        s.gx = gx; s.gxy = gx * gy;
        return s;
    };

    // 2) merged launch: VT = Wvh @ hh^T + bv (row bias)  [256 CTAs]
    //                   MT = WkT @ WqT^T                  [32 CTAs]
    {
        GemmSeg sVT = mkseg(Wvh, hh, 0, 0, 0, C_, C_, M_TOT, C_,
                            nullptr, VT, 1.0f, bv, 2, M_TOT / BN_, C_ / BM_);
        GemmSeg sMT = mkseg(WkT, WqT, 0, 0, 0, C_, C_, C_, C_,
                            nullptr, MT, 1.0f, nullptr, 0, C_ / BN_, C_ / BM_);
        int n0 = (M_TOT / BN_) * (C_ / BM_);   // 256
        int n1 = (C_ / BN_) * (C_ / BM_);      // 32
        gemm_seg<<<n0 + n1, 256, SMEM_GEMM>>>(sVT, sMT, n0);
    }
    // 3) QM = hh @ MT^T   [8192,1024] fp16   [256 CTAs]
    {
        GemmSeg s = mkseg(hh, MT, 0, 0, 0, C_, C_, C_, C_,
                          nullptr, QM, 1.0f, nullptr, 0, C_ / BN_, M_TOT / BM_);
        int n = s.gxy;
        gemm_seg<<<n, 256, SMEM_GEMM>>>(s, s, n);
    }
    // 4) scores = (QM_b @ hh_b^T)/32 -> fp32 attn (per batch)  [512 CTAs]
    {
        GemmSeg s = mkseg(QM, hh, (long long)N_ * C_, (long long)N_ * C_,
                          (long long)N_ * N_, C_, C_, N_, C_,
                          attn, nullptr, 1.0f / 32.0f, nullptr, 0, N_ / BN_, N_ / BM_);
        int n = s.gxy * B_;
        gemm_seg<<<n, 256, SMEM_GEMM>>>(s, s, n);
    }
    // 5) softmax (adds u/v/c rank-1 bias terms) + fp16 P
    softmax_h<<<B_ * N_, 256>>>(attn, P);

    // 6) out = P_b @ VT_b^T (per batch: M=2048, N=1024, K=2048)  [256 CTAs]
    {
        GemmSeg s = mkseg(P, VT, (long long)N_ * N_, (long long)N_,
                          (long long)N_ * C_, N_, M_TOT, C_, N_,
                          out, nullptr, 1.0f, nullptr, 0, C_ / BN_, N_ / BM_);
        int n = s.gxy * B_;
        gemm_seg<<<n, 256, SMEM_GEMM>>>(s, s, n);
    }
}

// round 11
// speedup vs baseline: 1.1892x; 1.0787x over previous
#include <cuda_runtime.h>
#include <cuda_fp16.h>
#include <math.h>
#include <stdint.h>

#define B_ 4
#define N_ 2048
#define C_ 1024
#define M_TOT (B_ * N_)   // 8192

// ---------------- scratch (__device__ globals; no allocation) ----------------
__device__ __align__(128) __half g_hh[(size_t)M_TOT * C_];
__device__ __align__(128) __half g_Wvh[C_ * C_];
__device__ __align__(128) __half g_WqT[C_ * C_];
__device__ __align__(128) __half g_WkT[C_ * C_];
__device__ __align__(128) __half g_MT[C_ * C_];
__device__ __align__(128) __half g_QM[(size_t)M_TOT * C_];
__device__ __align__(128) __half g_VT[(size_t)C_ * M_TOT];
__device__ __align__(128) __half g_P[(size_t)B_ * N_ * N_];
__device__ float g_w1p[8][C_], g_w2p[8][C_];      // partial W^T b sums
__device__ float g_u32[M_TOT], g_v32[M_TOT];
__device__ float g_cc;

// ---------------- portable PTX helpers (base-target safe) ----------------
__device__ __forceinline__ uint32_t smem_u32(const void* p) {
    uint32_t a;
    asm("{ .reg .u64 t; cvta.to.shared.u64 t, %1; cvt.u32.u64 %0, t; }" : "=r"(a) : "l"(p));
    return a;
}
__device__ __forceinline__ void cp_async16(uint32_t dst, const void* src) {
    asm volatile("cp.async.cg.shared.global [%0], [%1], 16;" :: "r"(dst), "l"(src) : "memory");
}
#define CP_COMMIT()  asm volatile("cp.async.commit_group;" ::: "memory")
#define CP_WAIT(n)   asm volatile("cp.async.wait_group %0;" :: "n"(n) : "memory")

__device__ __forceinline__ void ldsm_x4(uint32_t& r0, uint32_t& r1, uint32_t& r2, uint32_t& r3,
                                        uint32_t addr) {
    asm volatile("ldmatrix.sync.aligned.m8n8.x4.shared.b16 {%0,%1,%2,%3}, [%4];"
                 : "=r"(r0), "=r"(r1), "=r"(r2), "=r"(r3) : "r"(addr));
}
__device__ __forceinline__ void mma16816(float* d, const uint32_t* a, const uint32_t* b) {
    asm volatile(
        "mma.sync.aligned.m16n8k16.row.col.f32.f16.f16.f32 "
        "{%0,%1,%2,%3}, {%4,%5,%6,%7}, {%8,%9}, {%0,%1,%2,%3};"
        : "+f"(d[0]), "+f"(d[1]), "+f"(d[2]), "+f"(d[3])
        : "r"(a[0]), "r"(a[1]), "r"(a[2]), "r"(a[3]), "r"(b[0]), "r"(b[1]));
}
__device__ __forceinline__ uint32_t swz(uint32_t off) { return off ^ ((off >> 3) & 0x70); }

// ---------------- segmented fp16 GEMM: D = alpha*(A @ B^T) (+bias) ----------------
#define BM_ 128
#define BN_ 256
#define STAGES 3
#define TILE_A_BYTES 16384
#define STAGE_BYTES  49152
#define SMEM_GEMM (STAGES * STAGE_BYTES)   // 144 KB

struct GemmSeg {
    const __half* A; const __half* B;
    long long batA, batB, batC;
    int lda, ldb, ldc, K;
    float* Cf; __half* Ch;
    float alpha;
    const float* bias; int bias_mode;
    int gx, gxy;
};

__global__ __launch_bounds__(256, 1) void gemm_seg(GemmSeg s0, GemmSeg s1, int n0cnt)
{
    extern __shared__ char smem[];
    const uint32_t sbase = smem_u32(smem);
    const int tid  = threadIdx.x;
    const int wid  = tid >> 5;
    const int lane = tid & 31;

    const bool f = (int)blockIdx.x < n0cnt;
    const __half* Ag = f ? s0.A : s1.A;
    const __half* Bg = f ? s0.B : s1.B;
    const long long batA = f ? s0.batA : s1.batA;
    const long long batB = f ? s0.batB : s1.batB;
    const long long batC = f ? s0.batC : s1.batC;
    const int lda = f ? s0.lda : s1.lda;
    const int ldb = f ? s0.ldb : s1.ldb;
    const int ldc = f ? s0.ldc : s1.ldc;
    const int K   = f ? s0.K   : s1.K;
    float* Cf = f ? s0.Cf : s1.Cf;
    __half* Ch = f ? s0.Ch : s1.Ch;
    const float alpha = f ? s0.alpha : s1.alpha;
    const float* bias = f ? s0.bias : s1.bias;
    const int bias_mode = f ? s0.bias_mode : s1.bias_mode;
    const int gx  = f ? s0.gx  : s1.gx;
    const int gxy = f ? s0.gxy : s1.gxy;

    int lid = blockIdx.x - (f ? 0 : n0cnt);
    const long long bz = lid / gxy;
    int r = lid - (int)bz * gxy;
    const int m0 = (r / gx) * BM_;
    const int n0 = (r % gx) * BN_;

    const __half* Ap = Ag + bz * batA;
    const __half* Bp = Bg + bz * batB;

    const int wm = (wid >> 2) * 64;
    const int wn = (wid & 3) * 64;

    const int NK = K >> 6;

    const int lrow = tid >> 3;
    const int lch  = tid & 7;

    auto load_stage = [&](int kc, int s) {
        const __half* Asrc = Ap + (size_t)m0 * lda + kc * 64;
        const __half* Bsrc = Bp + (size_t)n0 * ldb + kc * 64;
        const uint32_t sa = sbase + s * STAGE_BYTES;
        const uint32_t sb = sa + TILE_A_BYTES;
        #pragma unroll
        for (int rr = 0; rr < 4; rr++) {
            int row = rr * 32 + lrow;
            uint32_t sw = swz(row * 128 + lch * 16);
            cp_async16(sa + sw, Asrc + (size_t)row * lda + lch * 8);
        }
        #pragma unroll
        for (int rr = 0; rr < 8; rr++) {
            int row = rr * 32 + lrow;
            uint32_t sw = swz(row * 128 + lch * 16);
            cp_async16(sb + sw, Bsrc + (size_t)row * ldb + lch * 8);
        }
        CP_COMMIT();
    };

    float acc[4][8][4];
    #pragma unroll
    for (int i = 0; i < 4; i++)
        #pragma unroll
        for (int j = 0; j < 8; j++)
            #pragma unroll
            for (int e = 0; e < 4; e++) acc[i][j][e] = 0.f;

    const int a_row_l = ((lane >> 3) & 1) * 8 + (lane & 7);
    const int a_col_l = ((lane >> 4) & 1) * 16;
    const int b_row_l = ((lane >> 4) & 1) * 8 + (lane & 7);
    const int b_col_l = ((lane >> 3) & 1) * 16;

    #pragma unroll
    for (int i = 0; i < STAGES; i++)
        if (i < NK) load_stage(i, i);

    int s = 0;
    for (int kc = 0; kc < NK; kc++) {
        int rem = NK - 1 - kc;
        if (rem >= 2)      { CP_WAIT(2); }
        else if (rem == 1) { CP_WAIT(1); }
        else               { CP_WAIT(0); }
        __syncthreads();

        const uint32_t cur_sa = sbase + s * STAGE_BYTES;
        const uint32_t cur_sb = cur_sa + TILE_A_BYTES;

        #pragma unroll
        for (int k16 = 0; k16 < 4; k16++) {
            uint32_t a[4][4], b[8][2];
            #pragma unroll
            for (int mt = 0; mt < 4; mt++) {
                uint32_t off = (uint32_t)(wm + mt * 16 + a_row_l) * 128 + k16 * 32 + a_col_l;
                ldsm_x4(a[mt][0], a[mt][1], a[mt][2], a[mt][3], cur_sa + swz(off));
            }
            #pragma unroll
            for (int nt2 = 0; nt2 < 4; nt2++) {
                uint32_t off = (uint32_t)(wn + nt2 * 16 + b_row_l) * 128 + k16 * 32 + b_col_l;
                uint32_t r0, r1, r2, r3;
                ldsm_x4(r0, r1, r2, r3, cur_sb + swz(off));
                b[nt2 * 2 + 0][0] = r0; b[nt2 * 2 + 0][1] = r1;
                b[nt2 * 2 + 1][0] = r2; b[nt2 * 2 + 1][1] = r3;
            }
            #pragma unroll
            for (int mt = 0; mt < 4; mt++)
                #pragma unroll
                for (int nt = 0; nt < 8; nt++)
                    mma16816(acc[mt][nt], a[mt], b[nt]);
        }

        __syncthreads();
        if (kc + STAGES < NK) load_stage(kc + STAGES, s);
        s++;
        if (s == STAGES) s = 0;
    }

    const int erow = lane >> 2;
    const int ecol = (lane & 3) * 2;

    #pragma unroll
    for (int mt = 0; mt < 4; mt++) {
        #pragma unroll
        for (int h = 0; h < 2; h++) {
            const int gm = m0 + wm + mt * 16 + h * 8 + erow;
            float brow = (bias_mode == 2) ? bias[gm] : 0.f;
            #pragma unroll
            for (int nt = 0; nt < 8; nt++) {
                const int gn = n0 + wn + nt * 8 + ecol;
                float x0 = acc[mt][nt][h * 2 + 0] * alpha;
                float x1 = acc[mt][nt][h * 2 + 1] * alpha;
                if (bias_mode == 1) { x0 += bias[gn]; x1 += bias[gn + 1]; }
                else if (bias_mode == 2) { x0 += brow; x1 += brow; }
                if (Cf) {
                    float2 v; v.x = x0; v.y = x1;
                    *(float2*)(Cf + bz * batC + (size_t)gm * ldc + gn) = v;
                } else {
                    __half2 hv = __floats2half2_rn(x0, x1);
                    *(__half2*)(Ch + bz * batC + (size_t)gm * ldc + gn) = hv;
                }
            }
        }
    }
}

// ---------------- elementwise / small kernels ----------------
// segmented cast: blocks < n0 -> (x0,y0), else (x1,y1)
__global__ __launch_bounds__(256) void cast_fp16_2(
    const float* __restrict__ x0, __half* __restrict__ y0,
    const float* __restrict__ x1, __half* __restrict__ y1, int n0)
{
    const bool f = (int)blockIdx.x < n0;
    const float* x = f ? x0 : x1;
    __half* y = f ? y0 : y1;
    size_t i = ((size_t)(f ? blockIdx.x : blockIdx.x - n0) * 256 + threadIdx.x);
    float4 v = *(const float4*)(x + i * 4);
    __half2 h0 = __floats2half2_rn(v.x, v.y);
    __half2 h1 = __floats2half2_rn(v.z, v.w);
    uint2 u;
    u.x = *(uint32_t*)&h0;
    u.y = *(uint32_t*)&h1;
    *(uint2*)(y + i * 4) = u;
}

// transpose + cast both Wq and Wk: z selects source
__global__ __launch_bounds__(256) void tcast2(
    const float* __restrict__ Wq, const float* __restrict__ Wk,
    __half* __restrict__ oq, __half* __restrict__ ok)
{
    __shared__ __half tile[32][33];
    const float* in = blockIdx.z ? Wk : Wq;
    __half* out = blockIdx.z ? ok : oq;
    const int bx = blockIdx.x * 32;
    const int by = blockIdx.y * 32;
    const int tx = threadIdx.x & 31;
    const int ty = threadIdx.x >> 5;
    #pragma unroll
    for (int i = 0; i < 32; i += 8)
        tile[ty + i][tx] = __float2half(in[(size_t)(by + ty + i) * C_ + bx + tx]);
    __syncthreads();
    #pragma unroll
    for (int i = 0; i < 32; i += 8)
        out[(size_t)(bx + ty + i) * C_ + by + tx] = tile[tx][ty + i];
}

// partial W^T b: 64 blocks for partials + 1 block for cc.
// block b in [0,32): Wq^T bk partial; [32,64): Wk^T bq partial; 64: cc.
__global__ __launch_bounds__(256) void wvec_p(
    const float* __restrict__ Wq, const float* __restrict__ Wk,
    const float* __restrict__ bq, const float* __restrict__ bk)
{
    const int bid = blockIdx.x;
    if (bid < 64) {
        const bool isq = bid < 32;
        const float* W = isq ? Wq : Wk;
        const float* bb = isq ? bk : bq;
        float* dst = isq ? &g_w1p[0][0] : &g_w2p[0][0];
        int lb = isq ? bid : bid - 32;
        int c = (lb & 3) * 256 + threadIdx.x;     // column
        int dchunk = lb >> 2;                     // 0..7
        float s = 0.f;
        #pragma unroll 4
        for (int d = dchunk * 128; d < dchunk * 128 + 128; d++)
            s += W[(size_t)d * C_ + c] * bb[d];
        dst[dchunk * C_ + c] = s;
    } else {
        const int tid = threadIdx.x;
        float s = 0.f;
        for (int d = tid; d < C_; d += 256) s += bq[d] * bk[d];
        __shared__ float red[8];
        #pragma unroll
        for (int off = 16; off > 0; off >>= 1)
            s += __shfl_xor_sync(0xffffffffu, s, off);
        if ((tid & 31) == 0) red[tid >> 5] = s;
        __syncthreads();
        if (tid == 0) {
            float t = 0.f;
            for (int w = 0; w < 8; w++) t += red[w];
            g_cc = t;
        }
    }
}

// u32[i] = (h_i.w1 + cc)/32 ; v32[i] = (h_i.w2)/32
__global__ __launch_bounds__(256) void uvvec(const __half* __restrict__ hh)
{
    __shared__ float w1s[C_], w2s[C_];
    const int tid = threadIdx.x;
    for (int i = tid; i < C_; i += 256) {
        float s1 = 0.f, s2 = 0.f;
        #pragma unroll
        for (int p = 0; p < 8; p++) { s1 += g_w1p[p][i]; s2 += g_w2p[p][i]; }
        w1s[i] = s1; w2s[i] = s2;
    }
    __syncthreads();
    const int lane = tid & 31;
    const int warp = tid >> 5;
    const int row = blockIdx.x * 8 + warp;
    const __half* hr = hh + (size_t)row * C_;
    float s1 = 0.f, s2 = 0.f;
    for (int k = lane; k < C_; k += 32) {
        float a = __half2float(hr[k]);
        s1 += a * w1s[k];
        s2 += a * w2s[k];
    }
    #pragma unroll
    for (int off = 16; off > 0; off >>= 1) {
        s1 += __shfl_xor_sync(0xffffffffu, s1, off);
        s2 += __shfl_xor_sync(0xffffffffu, s2, off);
    }
    if (lane == 0) {
        g_u32[row] = (s1 + g_cc) * (1.0f / 32.0f);
        g_v32[row] = s2 * (1.0f / 32.0f);
    }
}

// softmax over rows of 2048 (adds rank-1 bias terms), in-place fp32 + fp16 copy.
__global__ __launch_bounds__(256) void softmax_h(
    float* __restrict__ P, __half* __restrict__ Ph)
{
    const size_t row = blockIdx.x;
    float* p = P + row * (size_t)N_;
    __half* ph = Ph + row * (size_t)N_;
    const float* vb = g_v32 + (row >> 11 << 11);
    const float uadd = g_u32[row];
    const int tid = threadIdx.x;
    const int lane = tid & 31;
    const int warp = tid >> 5;

    float vals[8];
    float m = -INFINITY;
    #pragma unroll
    for (int i = 0; i < 8; i++) {
        int j = tid + i * 256;
        vals[i] = p[j] + uadd + vb[j];
        m = fmaxf(m, vals[i]);
    }
    __shared__ float redmax[8], redsum[8];
    #pragma unroll
    for (int off = 16; off > 0; off >>= 1)
        m = fmaxf(m, __shfl_xor_sync(0xffffffffu, m, off));
    if (lane == 0) redmax[warp] = m;
    __syncthreads();
    float rowmax = redmax[0];
    #pragma unroll
    for (int w = 1; w < 8; w++) rowmax = fmaxf(rowmax, redmax[w]);

    float sum = 0.f;
    #pragma unroll
    for (int i = 0; i < 8; i++) {
        vals[i] = __expf(vals[i] - rowmax);
        sum += vals[i];
    }
    #pragma unroll
    for (int off = 16; off > 0; off >>= 1)
        sum += __shfl_xor_sync(0xffffffffu, sum, off);
    if (lane == 0) redsum[warp] = sum;
    __syncthreads();
    float total = 0.f;
    #pragma unroll
    for (int w = 0; w < 8; w++) total += redsum[w];
    float inv = 1.f / total;

    #pragma unroll
    for (int i = 0; i < 8; i++) {
        float v = vals[i] * inv;
        p[tid + i * 256] = v;
        ph[tid + i * 256] = __float2half(v);
    }
}

// ---------------- launch ----------------
extern "C" void kernel_launch(void* const* d_in, const int* in_sizes, int n_in,
                              void* d_out, int out_size)
{
    const float* h  = (const float*)d_in[0];
    const float* Wq = (const float*)d_in[1];
    const float* bq = (const float*)d_in[2];
    const float* Wk = (const float*)d_in[3];
    const float* bk = (const float*)d_in[4];
    const float* Wv = (const float*)d_in[5];
    const float* bv = (const float*)d_in[6];

    float* out  = (float*)d_out;
    float* attn = out + (size_t)B_ * N_ * C_;

    __half *hh, *Wvh, *WqT, *WkT, *MT, *QM, *VT, *P;
    cudaGetSymbolAddress((void**)&hh,  g_hh);
    cudaGetSymbolAddress((void**)&Wvh, g_Wvh);
    cudaGetSymbolAddress((void**)&WqT, g_WqT);
    cudaGetSymbolAddress((void**)&WkT, g_WkT);
    cudaGetSymbolAddress((void**)&MT,  g_MT);
    cudaGetSymbolAddress((void**)&QM,  g_QM);
    cudaGetSymbolAddress((void**)&VT,  g_VT);
    cudaGetSymbolAddress((void**)&P,   g_P);

    cudaFuncSetAttribute(gemm_seg, cudaFuncAttributeMaxDynamicSharedMemorySize, SMEM_GEMM);

    // 1) casts / transposes / bias partials
    {
        int nh = (int)((size_t)M_TOT * C_ / 4 / 256);   // 8192 blocks
        int nw = (int)((size_t)C_ * C_ / 4 / 256);      // 1024 blocks
        cast_fp16_2<<<nh + nw, 256>>>(h, hh, Wv, Wvh, nh);
        dim3 tg(C_ / 32, C_ / 32, 2);
        tcast2<<<tg, 256>>>(Wq, Wk, WqT, WkT);
        wvec_p<<<65, 256>>>(Wq, Wk, bq, bk);
        uvvec<<<M_TOT / 8, 256>>>(hh);
    }

    auto mkseg = [](const __half* A, const __half* B, long long bA, long long bB,
                    long long bC, int lda, int ldb, int ldc, int K,
                    float* Cf, __half* Ch, float alpha,
                    const float* bias, int bias_mode, int gx, int gy) {
        GemmSeg s;
        s.A = A; s.B = B; s.batA = bA; s.batB = bB; s.batC = bC;
        s.lda = lda; s.ldb = ldb; s.ldc = ldc; s.K = K;
        s.Cf = Cf; s.Ch = Ch; s.alpha = alpha; s.bias = bias; s.bias_mode = bias_mode;
        s.gx = gx; s.gxy = gx * gy;
        return s;
    };

    // 2) merged: VT = Wvh @ hh^T + bv (row bias) [256] ; MT = WkT @ WqT^T [32]
    {
        GemmSeg sVT = mkseg(Wvh, hh, 0, 0, 0, C_, C_, M_TOT, C_,
                            nullptr, VT, 1.0f, bv, 2, M_TOT / BN_, C_ / BM_);
        GemmSeg sMT = mkseg(WkT, WqT, 0, 0, 0, C_, C_, C_, C_,
                            nullptr, MT, 1.0f, nullptr, 0, C_ / BN_, C_ / BM_);
        int n0 = (M_TOT / BN_) * (C_ / BM_);
        int n1 = (C_ / BN_) * (C_ / BM_);
        gemm_seg<<<n0 + n1, 256, SMEM_GEMM>>>(sVT, sMT, n0);
    }
    // 3) QM = hh @ MT^T  [256 CTAs]
    {
        GemmSeg s = mkseg(hh, MT, 0, 0, 0, C_, C_, C_, C_,
                          nullptr, QM, 1.0f, nullptr, 0, C_ / BN_, M_TOT / BM_);
        gemm_seg<<<s.gxy, 256, SMEM_GEMM>>>(s, s, s.gxy);
    }
    // 4) scores = (QM_b @ hh_b^T)/32 -> fp32 attn  [512 CTAs]
    {
        GemmSeg s = mkseg(QM, hh, (long long)N_ * C_, (long long)N_ * C_,
                          (long long)N_ * N_, C_, C_, N_, C_,
                          attn, nullptr, 1.0f / 32.0f, nullptr, 0, N_ / BN_, N_ / BM_);
        int n = s.gxy * B_;
        gemm_seg<<<n, 256, SMEM_GEMM>>>(s, s, n);
    }
    // 5) softmax + fp16 P
    softmax_h<<<B_ * N_, 256>>>(attn, P);

    // 6) out = P_b @ VT_b^T  [256 CTAs]
    {
        GemmSeg s = mkseg(P, VT, (long long)N_ * N_, (long long)N_,
                          (long long)N_ * C_, N_, M_TOT, C_, N_,
                          out, nullptr, 1.0f, nullptr, 0, C_ / BN_, N_ / BM_);
        int n = s.gxy * B_;
        gemm_seg<<<n, 256, SMEM_GEMM>>>(s, s, n);
    }
}